// round 11
// baseline (speedup 1.0000x reference)
#include <cuda_runtime.h>
#include <cuda_bf16.h>
#include <cstdint>
#include <cstdio>

#define NN 50000
#define NE 400000
#define HID 256
#define EDIM 768
#define NL 6

// ---------------- scratch ----------------
__device__ float g_hl[NN * HID];          // per-layer h @ Wc (GEMM out)
__device__ float g_ee[NL * NE];
__device__ float g_s[NN];
__device__ float g_d[NN];
__device__ float g_Ve[NL * EDIM];
__device__ float g_W12[HID * HID];
__device__ float g_W012[HID * HID];
__device__ float g_Wsum[HID * HID];
__device__ __nv_bfloat16 g_Ahi[NN * HID];
__device__ __nv_bfloat16 g_Alo[NN * HID];
__device__ __nv_bfloat16 g_Bthi[7 * HID * HID];
__device__ __nv_bfloat16 g_Btlo[7 * HID * HID];
// CSR (dst-sorted edges)
__device__ int g_deg[NN];
__device__ int g_rowptr[NN + 1];
__device__ int g_cur[NN];
__device__ int g_csrc[NE];
__device__ int g_ceid[NE];

// ---------------- fp32 SGEMM (weight precompute only, M=256) ----------------
__global__ __launch_bounds__(256) void sgemm128(
    const float* __restrict__ A, const float* __restrict__ B,
    float* __restrict__ C, int M)
{
    const int N = HID, K = HID;
    __shared__ float As[8][128];
    __shared__ float Bs[8][128];
    int tid = threadIdx.x;
    int bn = blockIdx.x * 128;
    int bm = blockIdx.y * 128;
    int arow = tid >> 1;
    int acol = (tid & 1) << 2;
    int brow = tid >> 5;
    int bcol = (tid & 31) << 2;
    int tx = tid & 15;
    int ty = tid >> 4;
    int grow = bm + arow;

    float acc[8][8];
#pragma unroll
    for (int i = 0; i < 8; i++)
#pragma unroll
        for (int j = 0; j < 8; j++) acc[i][j] = 0.f;

    for (int k0 = 0; k0 < K; k0 += 8) {
        float4 av = make_float4(0.f, 0.f, 0.f, 0.f);
        if (grow < M) av = *(const float4*)(A + (size_t)grow * K + k0 + acol);
        As[acol + 0][arow] = av.x;
        As[acol + 1][arow] = av.y;
        As[acol + 2][arow] = av.z;
        As[acol + 3][arow] = av.w;
        *(float4*)&Bs[brow][bcol] =
            *(const float4*)(B + (size_t)(k0 + brow) * N + bn + bcol);
        __syncthreads();
#pragma unroll
        for (int kk = 0; kk < 8; kk++) {
            float ra[8], rb[8];
            *(float4*)&ra[0] = *(const float4*)&As[kk][ty * 8];
            *(float4*)&ra[4] = *(const float4*)&As[kk][ty * 8 + 4];
            *(float4*)&rb[0] = *(const float4*)&Bs[kk][tx * 8];
            *(float4*)&rb[4] = *(const float4*)&Bs[kk][tx * 8 + 4];
#pragma unroll
            for (int i = 0; i < 8; i++)
#pragma unroll
                for (int j = 0; j < 8; j++)
                    acc[i][j] += ra[i] * rb[j];
        }
        __syncthreads();
    }
#pragma unroll
    for (int i = 0; i < 8; i++) {
        int r = bm + ty * 8 + i;
        if (r < M) {
            *(float4*)(C + (size_t)r * N + bn + tx * 8) =
                make_float4(acc[i][0], acc[i][1], acc[i][2], acc[i][3]);
            *(float4*)(C + (size_t)r * N + bn + tx * 8 + 4) =
                make_float4(acc[i][4], acc[i][5], acc[i][6], acc[i][7]);
        }
    }
}

// ---------------- bf16x3 tensor-core GEMM, preconverted operands ----------------
#define ASTR 40
#define STG  20480
#define AOLO 5120
#define AOBH 10240
#define AOBL 15360

__device__ __forceinline__ void mma16816(float* c, const uint32_t* a, const uint32_t* b) {
    asm volatile(
        "mma.sync.aligned.m16n8k16.row.col.f32.bf16.bf16.f32 "
        "{%0,%1,%2,%3}, {%4,%5,%6,%7}, {%8,%9}, {%0,%1,%2,%3};\n"
        : "+f"(c[0]), "+f"(c[1]), "+f"(c[2]), "+f"(c[3])
        : "r"(a[0]), "r"(a[1]), "r"(a[2]), "r"(a[3]), "r"(b[0]), "r"(b[1]));
}

__global__ __launch_bounds__(256) void mma_gemm2(
    const __nv_bfloat16* __restrict__ Ahi, const __nv_bfloat16* __restrict__ Alo,
    const __nv_bfloat16* __restrict__ Bhi, const __nv_bfloat16* __restrict__ Blo,
    float* __restrict__ C, int M)
{
    extern __shared__ __nv_bfloat16 sm[];
    const int tid = threadIdx.x;
    const int lane = tid & 31, wid = tid >> 5;
    const int warp_m = wid & 1, warp_n = wid >> 1;
    const int g = lane >> 2, t = lane & 3;
    const int bm = blockIdx.y * 128, bn = blockIdx.x * 128;

    float acc[4][4][4];
#pragma unroll
    for (int i = 0; i < 4; i++)
#pragma unroll
        for (int j = 0; j < 4; j++)
#pragma unroll
            for (int k = 0; k < 4; k++) acc[i][j][k] = 0.f;

    auto load_stage = [&](int k0, int s) {
        uint32_t base = (uint32_t)__cvta_generic_to_shared(sm + (size_t)s * STG);
#pragma unroll
        for (int i = 0; i < 2; i++) {
            int c = tid + 256 * i;
            int row = c >> 2, cc = c & 3;
            uint32_t doff = (uint32_t)(row * ASTR + cc * 8) * 2;
            size_t goff = (size_t)(bm + row) * HID + k0 + cc * 8;
            int szA = (bm + row) < M ? 16 : 0;
            asm volatile("cp.async.ca.shared.global [%0], [%1], 16, %2;\n"
                         :: "r"(base + doff), "l"(Ahi + goff), "r"(szA));
            asm volatile("cp.async.ca.shared.global [%0], [%1], 16, %2;\n"
                         :: "r"(base + AOLO * 2 + doff), "l"(Alo + goff), "r"(szA));
            size_t boff = (size_t)(bn + row) * HID + k0 + cc * 8;
            asm volatile("cp.async.ca.shared.global [%0], [%1], 16;\n"
                         :: "r"(base + AOBH * 2 + doff), "l"(Bhi + boff));
            asm volatile("cp.async.ca.shared.global [%0], [%1], 16;\n"
                         :: "r"(base + AOBL * 2 + doff), "l"(Blo + boff));
        }
        asm volatile("cp.async.commit_group;\n");
    };

    load_stage(0, 0);
    for (int k0i = 0; k0i < 8; k0i++) {
        if (k0i < 7) load_stage((k0i + 1) * 32, (k0i + 1) & 1);
        if (k0i < 7) asm volatile("cp.async.wait_group 1;\n");
        else         asm volatile("cp.async.wait_group 0;\n");
        __syncthreads();

        const __nv_bfloat16* sAhi = sm + (size_t)(k0i & 1) * STG;
        const __nv_bfloat16* sAlo = sAhi + AOLO;
        const __nv_bfloat16* sBhi = sAhi + AOBH;
        const __nv_bfloat16* sBlo = sAhi + AOBL;

#pragma unroll
        for (int ks = 0; ks < 32; ks += 16) {
            uint32_t afh[4][4], afl[4][4], bfh[4][2], bfl[4][2];
#pragma unroll
            for (int mt = 0; mt < 4; mt++) {
                int base = (warp_m * 64 + mt * 16 + g) * ASTR + ks + 2 * t;
                afh[mt][0] = *(const uint32_t*)&sAhi[base];
                afh[mt][1] = *(const uint32_t*)&sAhi[base + 8 * ASTR];
                afh[mt][2] = *(const uint32_t*)&sAhi[base + 8];
                afh[mt][3] = *(const uint32_t*)&sAhi[base + 8 * ASTR + 8];
                afl[mt][0] = *(const uint32_t*)&sAlo[base];
                afl[mt][1] = *(const uint32_t*)&sAlo[base + 8 * ASTR];
                afl[mt][2] = *(const uint32_t*)&sAlo[base + 8];
                afl[mt][3] = *(const uint32_t*)&sAlo[base + 8 * ASTR + 8];
            }
#pragma unroll
            for (int nt = 0; nt < 4; nt++) {
                int base = (warp_n * 32 + nt * 8 + g) * ASTR + ks + 2 * t;
                bfh[nt][0] = *(const uint32_t*)&sBhi[base];
                bfh[nt][1] = *(const uint32_t*)&sBhi[base + 8];
                bfl[nt][0] = *(const uint32_t*)&sBlo[base];
                bfl[nt][1] = *(const uint32_t*)&sBlo[base + 8];
            }
#pragma unroll
            for (int mt = 0; mt < 4; mt++)
#pragma unroll
                for (int nt = 0; nt < 4; nt++) {
                    mma16816(acc[mt][nt], afh[mt], bfh[nt]);
                    mma16816(acc[mt][nt], afh[mt], bfl[nt]);
                    mma16816(acc[mt][nt], afl[mt], bfh[nt]);
                }
        }
        __syncthreads();
    }

#pragma unroll
    for (int mt = 0; mt < 4; mt++) {
        int row = bm + warp_m * 64 + mt * 16 + g;
#pragma unroll
        for (int nt = 0; nt < 4; nt++) {
            int col = bn + warp_n * 32 + nt * 8 + 2 * t;
            if (row < M)
                *(float2*)(C + (size_t)row * HID + col) =
                    make_float2(acc[mt][nt][0], acc[mt][nt][1]);
            if (row + 8 < M)
                *(float2*)(C + (size_t)(row + 8) * HID + col) =
                    make_float2(acc[mt][nt][2], acc[mt][nt][3]);
        }
    }
}

// ---------------- split kernels ----------------
__global__ void split_plain(const float* __restrict__ h,
                            __nv_bfloat16* __restrict__ hi,
                            __nv_bfloat16* __restrict__ lo) {
    int i = blockIdx.x * blockDim.x + threadIdx.x;
    if (i >= NN * HID / 4) return;
    float4 v = ((const float4*)h)[i];
    float vv[4] = {v.x, v.y, v.z, v.w};
    __nv_bfloat16 h4[4], l4[4];
#pragma unroll
    for (int j = 0; j < 4; j++) {
        h4[j] = __float2bfloat16_rn(vv[j]);
        l4[j] = __float2bfloat16_rn(vv[j] - __bfloat162float(h4[j]));
    }
    ((uint2*)hi)[i] = *(uint2*)h4;
    ((uint2*)lo)[i] = *(uint2*)l4;
}

__global__ void split_W(const float* __restrict__ W012, const float* __restrict__ Wc,
                        const float* __restrict__ Wsum,
                        __nv_bfloat16* __restrict__ hi, __nv_bfloat16* __restrict__ lo) {
    int i = blockIdx.x * blockDim.x + threadIdx.x;
    if (i >= 7 * HID * HID) return;
    int slot = i >> 16, r = i & 65535;
    int n = r >> 8, k = r & 255;
    const float* src = (slot == 0) ? W012
                     : (slot <= 5) ? Wc + (size_t)slot * HID * HID
                                   : Wsum;
    float v = src[k * HID + n];
    __nv_bfloat16 h = __float2bfloat16_rn(v);
    hi[i] = h;
    lo[i] = __float2bfloat16_rn(v - __bfloat162float(h));
}

// ---------------- precompute kernels ----------------
__global__ void wsum_kernel(const float* __restrict__ W3, float* __restrict__ Wsum) {
    int i = blockIdx.x * blockDim.x + threadIdx.x;
    if (i < HID * HID) Wsum[i] = W3[i] + W3[i + HID * HID];
}

__global__ void compute_Ve(const float* __restrict__ We, const float* __restrict__ a_e,
                           float* __restrict__ Ve) {
    int w = (blockIdx.x * blockDim.x + threadIdx.x) >> 5;
    int lane = threadIdx.x & 31;
    if (w >= NL * EDIM) return;
    int l = w / EDIM, j = w % EDIM;
    const float4* wr = (const float4*)(We + ((size_t)l * EDIM + j) * HID);
    const float4* ar = (const float4*)(a_e + (size_t)l * HID);
    float s = 0.f;
#pragma unroll
    for (int i = 0; i < 2; i++) {
        float4 x = wr[lane + 32 * i];
        float4 y = ar[lane + 32 * i];
        s += x.x * y.x + x.y * y.y + x.z * y.z + x.w * y.w;
    }
#pragma unroll
    for (int o = 16; o; o >>= 1) s += __shfl_xor_sync(~0u, s, o);
    if (!lane) Ve[l * EDIM + j] = s;
}

__global__ __launch_bounds__(256) void edge_dots(const float* __restrict__ edge_attr,
                                                 float* __restrict__ out) {
    __shared__ float4 sVe[NL][EDIM / 4];
    for (int i = threadIdx.x; i < NL * EDIM / 4; i += blockDim.x)
        ((float4*)sVe)[i] = ((const float4*)g_Ve)[i];
    __syncthreads();
    int w = (blockIdx.x * blockDim.x + threadIdx.x) >> 5;
    int lane = threadIdx.x & 31;
    if (w >= NE) return;
    const float4* row = (const float4*)(edge_attr + (size_t)w * EDIM);
    float acc[NL] = {0.f, 0.f, 0.f, 0.f, 0.f, 0.f};
#pragma unroll
    for (int i = 0; i < 6; i++) {
        int p = lane + 32 * i;
        float4 v = row[p];
#pragma unroll
        for (int l = 0; l < NL; l++) {
            float4 u = sVe[l][p];
            acc[l] += v.x * u.x + v.y * u.y + v.z * u.z + v.w * u.w;
        }
    }
#pragma unroll
    for (int l = 0; l < NL; l++) {
        float a = acc[l];
#pragma unroll
        for (int o = 16; o; o >>= 1) a += __shfl_xor_sync(~0u, a, o);
        if (!lane) out[(size_t)l * NE + w] = a;
    }
}

__global__ void node_dots(const float* __restrict__ h, const float* __restrict__ as_,
                          const float* __restrict__ ad_, float* __restrict__ s,
                          float* __restrict__ d) {
    int w = (blockIdx.x * blockDim.x + threadIdx.x) >> 5;
    int lane = threadIdx.x & 31;
    if (w >= NN) return;
    const float4* row = (const float4*)(h + (size_t)w * HID);
    const float4* A = (const float4*)as_;
    const float4* D = (const float4*)ad_;
    float ss = 0.f, dd = 0.f;
#pragma unroll
    for (int i = 0; i < 2; i++) {
        float4 v = row[lane + 32 * i];
        float4 a = A[lane + 32 * i];
        float4 b = D[lane + 32 * i];
        ss += v.x * a.x + v.y * a.y + v.z * a.z + v.w * a.w;
        dd += v.x * b.x + v.y * b.y + v.z * b.z + v.w * b.w;
    }
#pragma unroll
    for (int o = 16; o; o >>= 1) {
        ss += __shfl_xor_sync(~0u, ss, o);
        dd += __shfl_xor_sync(~0u, dd, o);
    }
    if (!lane) { s[w] = ss; d[w] = dd; }
}

// ---------------- CSR build ----------------
__global__ void zero_int(int* __restrict__ p, int n) {
    int i = blockIdx.x * blockDim.x + threadIdx.x;
    if (i < n) p[i] = 0;
}

__global__ void hist_deg(const int* __restrict__ ei, int* __restrict__ deg) {
    int e = blockIdx.x * blockDim.x + threadIdx.x;
    if (e < NE) atomicAdd(&deg[ei[NE + e]], 1);
}

__global__ __launch_bounds__(1024) void scan_deg(const int* __restrict__ deg,
                                                 int* __restrict__ rowptr) {
    const int CH = (NN + 1023) / 1024;     // 49
    int tid = threadIdx.x;
    int lane = tid & 31, wid = tid >> 5;
    int base = tid * CH;
    int s = 0;
    for (int k = 0; k < CH; k++) {
        int idx = base + k;
        if (idx < NN) s += deg[idx];
    }
    __shared__ int wsum[32];
    int v = s;
#pragma unroll
    for (int o = 1; o < 32; o <<= 1) {
        int t = __shfl_up_sync(~0u, v, o);
        if (lane >= o) v += t;
    }
    if (lane == 31) wsum[wid] = v;
    __syncthreads();
    if (wid == 0) {
        int w = wsum[lane];
#pragma unroll
        for (int o = 1; o < 32; o <<= 1) {
            int t = __shfl_up_sync(~0u, w, o);
            if (lane >= o) w += t;
        }
        wsum[lane] = w;
    }
    __syncthreads();
    int excl = v - s + (wid > 0 ? wsum[wid - 1] : 0);
    int run = excl;
    for (int k = 0; k < CH; k++) {
        int idx = base + k;
        if (idx < NN) { rowptr[idx] = run; run += deg[idx]; }
    }
    if (tid == 1023) rowptr[NN] = run;
}

__global__ void copy_int(const int* __restrict__ a, int* __restrict__ b, int n) {
    int i = blockIdx.x * blockDim.x + threadIdx.x;
    if (i < n) b[i] = a[i];
}

__global__ void csr_fill(const int* __restrict__ ei, int* __restrict__ cur,
                         int* __restrict__ csrc, int* __restrict__ ceid) {
    int e = blockIdx.x * blockDim.x + threadIdx.x;
    if (e >= NE) return;
    int src = ei[e], dst = ei[NE + e];
    int pos = atomicAdd(&cur[dst], 1);
    csrc[pos] = src;
    ceid[pos] = e;
}

// ---------------- fused GAT aggregation: warp per dst node ----------------
// out_row = (sum_e ea_e * hl[src_e]) / (sum_e ea_e + 1e-16) + bias, opt relu,
// then bf16 split directly into Ahi/Alo for the next GEMM.
__global__ __launch_bounds__(256) void gat_agg(
    const int* __restrict__ rowptr, const int* __restrict__ csrc,
    const int* __restrict__ ceid, const float* __restrict__ hl,
    const float* __restrict__ s, const float* __restrict__ d,
    const float* __restrict__ ee, const float* __restrict__ bias,
    int relu, __nv_bfloat16* __restrict__ Ahi, __nv_bfloat16* __restrict__ Alo)
{
    int w = (blockIdx.x * blockDim.x + threadIdx.x) >> 5;
    int lane = threadIdx.x & 31;
    if (w >= NN) return;
    int start = rowptr[w];
    int deg = rowptr[w + 1] - start;
    float dn = d[w];

    // pass 1: max of leaky-relu(alpha)
    float m = -1e30f;
    for (int i = lane; i < deg; i += 32) {
        int src = csrc[start + i];
        float a = s[src] + dn + ee[ceid[start + i]];
        a = a > 0.f ? a : 0.2f * a;
        m = fmaxf(m, a);
    }
#pragma unroll
    for (int o = 16; o; o >>= 1) m = fmaxf(m, __shfl_xor_sync(~0u, m, o));

    // pass 2: accumulate sum(ea) and sum(ea * h[src])
    float4 acc0 = make_float4(0.f, 0.f, 0.f, 0.f);
    float4 acc1 = make_float4(0.f, 0.f, 0.f, 0.f);
    float den = 0.f;
    const float4* hl4 = (const float4*)hl;
    for (int base = 0; base < deg; base += 32) {
        int i = base + lane;
        float ea = 0.f;
        int src = 0;
        if (i < deg) {
            src = csrc[start + i];
            float a = s[src] + dn + ee[ceid[start + i]];
            a = a > 0.f ? a : 0.2f * a;
            ea = __expf(a - m);
        }
        den += ea;
        int cnt = min(32, deg - base);
        for (int j = 0; j < cnt; j++) {
            float c = __shfl_sync(~0u, ea, j);
            int sj = __shfl_sync(~0u, src, j);
            float4 v0 = hl4[(size_t)sj * 64 + lane];
            float4 v1 = hl4[(size_t)sj * 64 + 32 + lane];
            acc0.x += c * v0.x; acc0.y += c * v0.y;
            acc0.z += c * v0.z; acc0.w += c * v0.w;
            acc1.x += c * v1.x; acc1.y += c * v1.y;
            acc1.z += c * v1.z; acc1.w += c * v1.w;
        }
    }
#pragma unroll
    for (int o = 16; o; o >>= 1) den += __shfl_xor_sync(~0u, den, o);
    float inv = 1.f / (den + 1e-16f);

    float4 b0 = ((const float4*)bias)[lane];
    float4 b1 = ((const float4*)bias)[32 + lane];
    float o0[4] = {acc0.x * inv + b0.x, acc0.y * inv + b0.y,
                   acc0.z * inv + b0.z, acc0.w * inv + b0.w};
    float o1[4] = {acc1.x * inv + b1.x, acc1.y * inv + b1.y,
                   acc1.z * inv + b1.z, acc1.w * inv + b1.w};
    if (relu) {
#pragma unroll
        for (int j = 0; j < 4; j++) {
            o0[j] = fmaxf(o0[j], 0.f);
            o1[j] = fmaxf(o1[j], 0.f);
        }
    }
    __nv_bfloat16 h0[4], l0[4], h1[4], l1[4];
#pragma unroll
    for (int j = 0; j < 4; j++) {
        h0[j] = __float2bfloat16_rn(o0[j]);
        l0[j] = __float2bfloat16_rn(o0[j] - __bfloat162float(h0[j]));
        h1[j] = __float2bfloat16_rn(o1[j]);
        l1[j] = __float2bfloat16_rn(o1[j] - __bfloat162float(h1[j]));
    }
    ((uint2*)Ahi)[(size_t)w * 64 + lane]      = *(uint2*)h0;
    ((uint2*)Ahi)[(size_t)w * 64 + 32 + lane] = *(uint2*)h1;
    ((uint2*)Alo)[(size_t)w * 64 + lane]      = *(uint2*)l0;
    ((uint2*)Alo)[(size_t)w * 64 + 32 + lane] = *(uint2*)l1;
}

// ---------------- launch ----------------
extern "C" void kernel_launch(void* const* d_in, const int* in_sizes, int n_in,
                              void* d_out, int out_size) {
    const float* x    = (const float*)d_in[0];
    const int*   ei   = (const int*)d_in[1];
    const float* eatt = (const float*)d_in[2];
    const float* W1   = (const float*)d_in[3];
    const float* W2   = (const float*)d_in[4];
    const float* Wc   = (const float*)d_in[5];
    const float* We   = (const float*)d_in[6];
    const float* a_s  = (const float*)d_in[7];
    const float* a_d  = (const float*)d_in[8];
    const float* a_e  = (const float*)d_in[9];
    const float* bias = (const float*)d_in[10];
    const float* W3   = (const float*)d_in[11];
    float*       out  = (float*)d_out;

    float *p_hl, *p_ee, *p_s, *p_d, *p_Ve, *p_W12, *p_W012, *p_Ws;
    __nv_bfloat16 *p_Ahi, *p_Alo, *p_Bthi, *p_Btlo;
    int *p_deg, *p_rowptr, *p_cur, *p_csrc, *p_ceid;
    cudaGetSymbolAddress((void**)&p_hl, g_hl);
    cudaGetSymbolAddress((void**)&p_ee, g_ee);
    cudaGetSymbolAddress((void**)&p_s, g_s);
    cudaGetSymbolAddress((void**)&p_d, g_d);
    cudaGetSymbolAddress((void**)&p_Ve, g_Ve);
    cudaGetSymbolAddress((void**)&p_W12, g_W12);
    cudaGetSymbolAddress((void**)&p_W012, g_W012);
    cudaGetSymbolAddress((void**)&p_Ws, g_Wsum);
    cudaGetSymbolAddress((void**)&p_Ahi, g_Ahi);
    cudaGetSymbolAddress((void**)&p_Alo, g_Alo);
    cudaGetSymbolAddress((void**)&p_Bthi, g_Bthi);
    cudaGetSymbolAddress((void**)&p_Btlo, g_Btlo);
    cudaGetSymbolAddress((void**)&p_deg, g_deg);
    cudaGetSymbolAddress((void**)&p_rowptr, g_rowptr);
    cudaGetSymbolAddress((void**)&p_cur, g_cur);
    cudaGetSymbolAddress((void**)&p_csrc, g_csrc);
    cudaGetSymbolAddress((void**)&p_ceid, g_ceid);

    cudaFuncSetAttribute(mma_gemm2, cudaFuncAttributeMaxDynamicSharedMemorySize,
                         2 * STG * (int)sizeof(__nv_bfloat16));
    const size_t smem_sz = 2 * STG * sizeof(__nv_bfloat16);

    const int MBY = (NN + 127) / 128;
    const dim3 gemm_grid(2, MBY);

    // ---- one-time precompute ----
    sgemm128<<<dim3(2, 2), 256>>>(W1, W2, p_W12, HID);
    sgemm128<<<dim3(2, 2), 256>>>(p_W12, Wc, p_W012, HID);
    wsum_kernel<<<(HID * HID + 255) / 256, 256>>>(W3, p_Ws);
    split_W<<<(7 * HID * HID + 255) / 256, 256>>>(p_W012, Wc, p_Ws, p_Bthi, p_Btlo);
    compute_Ve<<<(NL * EDIM * 32 + 255) / 256, 256>>>(We, a_e, p_Ve);
    edge_dots<<<(NE * 32 + 255) / 256, 256>>>(eatt, p_ee);

    // CSR build
    zero_int<<<(NN + 255) / 256, 256>>>(p_deg, NN);
    hist_deg<<<(NE + 255) / 256, 256>>>(ei, p_deg);
    scan_deg<<<1, 1024>>>(p_deg, p_rowptr);
    copy_int<<<(NN + 255) / 256, 256>>>(p_rowptr, p_cur, NN);
    csr_fill<<<(NE + 255) / 256, 256>>>(ei, p_cur, p_csrc, p_ceid);

    // A = split(x)
    split_plain<<<(NN * HID / 4 + 255) / 256, 256>>>(x, p_Ahi, p_Alo);

    for (int l = 0; l < NL; l++) {
        mma_gemm2<<<gemm_grid, 256, smem_sz>>>(
            p_Ahi, p_Alo,
            p_Bthi + (size_t)l * HID * HID, p_Btlo + (size_t)l * HID * HID,
            p_hl, NN);
        node_dots<<<(NN * 32 + 255) / 256, 256>>>(p_hl, a_s + l * HID, a_d + l * HID,
                                                  p_s, p_d);
        gat_agg<<<(NN * 32 + 255) / 256, 256>>>(
            p_rowptr, p_csrc, p_ceid, p_hl, p_s, p_d,
            p_ee + (size_t)l * NE, bias + l * HID,
            (l == NL - 1) ? 1 : 0, p_Ahi, p_Alo);
    }

    // out = relu(h) @ (W3a + W3b)
    mma_gemm2<<<gemm_grid, 256, smem_sz>>>(
        p_Ahi, p_Alo,
        p_Bthi + (size_t)6 * HID * HID, p_Btlo + (size_t)6 * HID * HID,
        out, NN);
}

// round 14
// speedup vs baseline: 1.3098x; 1.3098x over previous
#include <cuda_runtime.h>
#include <cuda_bf16.h>
#include <cstdint>
#include <cstdio>

#define NN 50000
#define NE 400000
#define HID 256
#define EDIM 768
#define NL 6

// ---------------- scratch ----------------
__device__ float g_hl[NN * HID];          // per-layer h @ Wc (GEMM out)
__device__ float g_hn[NN * HID];          // scatter accumulator (unnormalized)
__device__ float g_ee[NL * NE];
__device__ float g_ea[NE];                // leaky-relu alpha per edge
__device__ float g_s[NN];
__device__ float g_d[NN];
__device__ float g_mx[NN];
__device__ float g_dn[NN];
__device__ float g_Ve[NL * EDIM];
__device__ float g_W12[HID * HID];
__device__ float g_W012[HID * HID];
__device__ float g_Wsum[HID * HID];
__device__ __nv_bfloat16 g_Ahi[NN * HID];
__device__ __nv_bfloat16 g_Alo[NN * HID];
__device__ __nv_bfloat16 g_Bthi[7 * HID * HID];
__device__ __nv_bfloat16 g_Btlo[7 * HID * HID];

__device__ __forceinline__ void atomicMaxF(float* addr, float val) {
    if (val >= 0.f) atomicMax((int*)addr, __float_as_int(val));
    else            atomicMin((unsigned int*)addr, __float_as_uint(val));
}

// ---------------- fp32 SGEMM (weight precompute only, M=256) ----------------
__global__ __launch_bounds__(256) void sgemm128(
    const float* __restrict__ A, const float* __restrict__ B,
    float* __restrict__ C, int M)
{
    const int N = HID, K = HID;
    __shared__ float As[8][128];
    __shared__ float Bs[8][128];
    int tid = threadIdx.x;
    int bn = blockIdx.x * 128;
    int bm = blockIdx.y * 128;
    int arow = tid >> 1;
    int acol = (tid & 1) << 2;
    int brow = tid >> 5;
    int bcol = (tid & 31) << 2;
    int tx = tid & 15;
    int ty = tid >> 4;
    int grow = bm + arow;

    float acc[8][8];
#pragma unroll
    for (int i = 0; i < 8; i++)
#pragma unroll
        for (int j = 0; j < 8; j++) acc[i][j] = 0.f;

    for (int k0 = 0; k0 < K; k0 += 8) {
        float4 av = make_float4(0.f, 0.f, 0.f, 0.f);
        if (grow < M) av = *(const float4*)(A + (size_t)grow * K + k0 + acol);
        As[acol + 0][arow] = av.x;
        As[acol + 1][arow] = av.y;
        As[acol + 2][arow] = av.z;
        As[acol + 3][arow] = av.w;
        *(float4*)&Bs[brow][bcol] =
            *(const float4*)(B + (size_t)(k0 + brow) * N + bn + bcol);
        __syncthreads();
#pragma unroll
        for (int kk = 0; kk < 8; kk++) {
            float ra[8], rb[8];
            *(float4*)&ra[0] = *(const float4*)&As[kk][ty * 8];
            *(float4*)&ra[4] = *(const float4*)&As[kk][ty * 8 + 4];
            *(float4*)&rb[0] = *(const float4*)&Bs[kk][tx * 8];
            *(float4*)&rb[4] = *(const float4*)&Bs[kk][tx * 8 + 4];
#pragma unroll
            for (int i = 0; i < 8; i++)
#pragma unroll
                for (int j = 0; j < 8; j++)
                    acc[i][j] += ra[i] * rb[j];
        }
        __syncthreads();
    }
#pragma unroll
    for (int i = 0; i < 8; i++) {
        int r = bm + ty * 8 + i;
        if (r < M) {
            *(float4*)(C + (size_t)r * N + bn + tx * 8) =
                make_float4(acc[i][0], acc[i][1], acc[i][2], acc[i][3]);
            *(float4*)(C + (size_t)r * N + bn + tx * 8 + 4) =
                make_float4(acc[i][4], acc[i][5], acc[i][6], acc[i][7]);
        }
    }
}

// ---------------- bf16x3 tensor-core GEMM, preconverted operands ----------------
#define ASTR 40
#define STG  20480
#define AOLO 5120
#define AOBH 10240
#define AOBL 15360

__device__ __forceinline__ void mma16816(float* c, const uint32_t* a, const uint32_t* b) {
    asm volatile(
        "mma.sync.aligned.m16n8k16.row.col.f32.bf16.bf16.f32 "
        "{%0,%1,%2,%3}, {%4,%5,%6,%7}, {%8,%9}, {%0,%1,%2,%3};\n"
        : "+f"(c[0]), "+f"(c[1]), "+f"(c[2]), "+f"(c[3])
        : "r"(a[0]), "r"(a[1]), "r"(a[2]), "r"(a[3]), "r"(b[0]), "r"(b[1]));
}

__global__ __launch_bounds__(256) void mma_gemm2(
    const __nv_bfloat16* __restrict__ Ahi, const __nv_bfloat16* __restrict__ Alo,
    const __nv_bfloat16* __restrict__ Bhi, const __nv_bfloat16* __restrict__ Blo,
    float* __restrict__ C, int M)
{
    extern __shared__ __nv_bfloat16 sm[];
    const int tid = threadIdx.x;
    const int lane = tid & 31, wid = tid >> 5;
    const int warp_m = wid & 1, warp_n = wid >> 1;
    const int g = lane >> 2, t = lane & 3;
    const int bm = blockIdx.y * 128, bn = blockIdx.x * 128;

    float acc[4][4][4];
#pragma unroll
    for (int i = 0; i < 4; i++)
#pragma unroll
        for (int j = 0; j < 4; j++)
#pragma unroll
            for (int k = 0; k < 4; k++) acc[i][j][k] = 0.f;

    auto load_stage = [&](int k0, int s) {
        uint32_t base = (uint32_t)__cvta_generic_to_shared(sm + (size_t)s * STG);
#pragma unroll
        for (int i = 0; i < 2; i++) {
            int c = tid + 256 * i;
            int row = c >> 2, cc = c & 3;
            uint32_t doff = (uint32_t)(row * ASTR + cc * 8) * 2;
            size_t goff = (size_t)(bm + row) * HID + k0 + cc * 8;
            int szA = (bm + row) < M ? 16 : 0;
            asm volatile("cp.async.ca.shared.global [%0], [%1], 16, %2;\n"
                         :: "r"(base + doff), "l"(Ahi + goff), "r"(szA));
            asm volatile("cp.async.ca.shared.global [%0], [%1], 16, %2;\n"
                         :: "r"(base + AOLO * 2 + doff), "l"(Alo + goff), "r"(szA));
            size_t boff = (size_t)(bn + row) * HID + k0 + cc * 8;
            asm volatile("cp.async.ca.shared.global [%0], [%1], 16;\n"
                         :: "r"(base + AOBH * 2 + doff), "l"(Bhi + boff));
            asm volatile("cp.async.ca.shared.global [%0], [%1], 16;\n"
                         :: "r"(base + AOBL * 2 + doff), "l"(Blo + boff));
        }
        asm volatile("cp.async.commit_group;\n");
    };

    load_stage(0, 0);
    for (int k0i = 0; k0i < 8; k0i++) {
        if (k0i < 7) load_stage((k0i + 1) * 32, (k0i + 1) & 1);
        if (k0i < 7) asm volatile("cp.async.wait_group 1;\n");
        else         asm volatile("cp.async.wait_group 0;\n");
        __syncthreads();

        const __nv_bfloat16* sAhi = sm + (size_t)(k0i & 1) * STG;
        const __nv_bfloat16* sAlo = sAhi + AOLO;
        const __nv_bfloat16* sBhi = sAhi + AOBH;
        const __nv_bfloat16* sBlo = sAhi + AOBL;

#pragma unroll
        for (int ks = 0; ks < 32; ks += 16) {
            uint32_t afh[4][4], afl[4][4], bfh[4][2], bfl[4][2];
#pragma unroll
            for (int mt = 0; mt < 4; mt++) {
                int base = (warp_m * 64 + mt * 16 + g) * ASTR + ks + 2 * t;
                afh[mt][0] = *(const uint32_t*)&sAhi[base];
                afh[mt][1] = *(const uint32_t*)&sAhi[base + 8 * ASTR];
                afh[mt][2] = *(const uint32_t*)&sAhi[base + 8];
                afh[mt][3] = *(const uint32_t*)&sAhi[base + 8 * ASTR + 8];
                afl[mt][0] = *(const uint32_t*)&sAlo[base];
                afl[mt][1] = *(const uint32_t*)&sAlo[base + 8 * ASTR];
                afl[mt][2] = *(const uint32_t*)&sAlo[base + 8];
                afl[mt][3] = *(const uint32_t*)&sAlo[base + 8 * ASTR + 8];
            }
#pragma unroll
            for (int nt = 0; nt < 4; nt++) {
                int base = (warp_n * 32 + nt * 8 + g) * ASTR + ks + 2 * t;
                bfh[nt][0] = *(const uint32_t*)&sBhi[base];
                bfh[nt][1] = *(const uint32_t*)&sBhi[base + 8];
                bfl[nt][0] = *(const uint32_t*)&sBlo[base];
                bfl[nt][1] = *(const uint32_t*)&sBlo[base + 8];
            }
#pragma unroll
            for (int mt = 0; mt < 4; mt++)
#pragma unroll
                for (int nt = 0; nt < 4; nt++) {
                    mma16816(acc[mt][nt], afh[mt], bfh[nt]);
                    mma16816(acc[mt][nt], afh[mt], bfl[nt]);
                    mma16816(acc[mt][nt], afl[mt], bfh[nt]);
                }
        }
        __syncthreads();
    }

#pragma unroll
    for (int mt = 0; mt < 4; mt++) {
        int row = bm + warp_m * 64 + mt * 16 + g;
#pragma unroll
        for (int nt = 0; nt < 4; nt++) {
            int col = bn + warp_n * 32 + nt * 8 + 2 * t;
            if (row < M)
                *(float2*)(C + (size_t)row * HID + col) =
                    make_float2(acc[mt][nt][0], acc[mt][nt][1]);
            if (row + 8 < M)
                *(float2*)(C + (size_t)(row + 8) * HID + col) =
                    make_float2(acc[mt][nt][2], acc[mt][nt][3]);
        }
    }
}

// ---------------- split / finalize ----------------
// finalize: h = hn / (dn + 1e-16) + bias (opt relu), then bf16 split.
// When dn==nullptr: h = input (+bias if given), used for the initial x split.
__global__ void split_bias(const float* __restrict__ h, const float* __restrict__ dn,
                           const float* __restrict__ b, int relu,
                           __nv_bfloat16* __restrict__ hi,
                           __nv_bfloat16* __restrict__ lo) {
    int i = blockIdx.x * blockDim.x + threadIdx.x;
    if (i >= NN * HID / 4) return;
    float4 v = ((const float4*)h)[i];
    if (dn) {
        float inv = 1.f / (dn[i >> 6] + 1e-16f);
        v.x *= inv; v.y *= inv; v.z *= inv; v.w *= inv;
    }
    if (b) {
        float4 bb = ((const float4*)b)[i & 63];
        v.x += bb.x; v.y += bb.y; v.z += bb.z; v.w += bb.w;
    }
    if (relu) {
        v.x = fmaxf(v.x, 0.f); v.y = fmaxf(v.y, 0.f);
        v.z = fmaxf(v.z, 0.f); v.w = fmaxf(v.w, 0.f);
    }
    float vv[4] = {v.x, v.y, v.z, v.w};
    __nv_bfloat16 h4[4], l4[4];
#pragma unroll
    for (int j = 0; j < 4; j++) {
        h4[j] = __float2bfloat16_rn(vv[j]);
        l4[j] = __float2bfloat16_rn(vv[j] - __bfloat162float(h4[j]));
    }
    ((uint2*)hi)[i] = *(uint2*)h4;
    ((uint2*)lo)[i] = *(uint2*)l4;
}

__global__ void split_W(const float* __restrict__ W012, const float* __restrict__ Wc,
                        const float* __restrict__ Wsum,
                        __nv_bfloat16* __restrict__ hi, __nv_bfloat16* __restrict__ lo) {
    int i = blockIdx.x * blockDim.x + threadIdx.x;
    if (i >= 7 * HID * HID) return;
    int slot = i >> 16, r = i & 65535;
    int n = r >> 8, k = r & 255;
    const float* src = (slot == 0) ? W012
                     : (slot <= 5) ? Wc + (size_t)slot * HID * HID
                                   : Wsum;
    float v = src[k * HID + n];
    __nv_bfloat16 h = __float2bfloat16_rn(v);
    hi[i] = h;
    lo[i] = __float2bfloat16_rn(v - __bfloat162float(h));
}

// ---------------- precompute kernels ----------------
__global__ void wsum_kernel(const float* __restrict__ W3, float* __restrict__ Wsum) {
    int i = blockIdx.x * blockDim.x + threadIdx.x;
    if (i < HID * HID) Wsum[i] = W3[i] + W3[i + HID * HID];
}

__global__ void compute_Ve(const float* __restrict__ We, const float* __restrict__ a_e,
                           float* __restrict__ Ve) {
    int w = (blockIdx.x * blockDim.x + threadIdx.x) >> 5;
    int lane = threadIdx.x & 31;
    if (w >= NL * EDIM) return;
    int l = w / EDIM, j = w % EDIM;
    const float4* wr = (const float4*)(We + ((size_t)l * EDIM + j) * HID);
    const float4* ar = (const float4*)(a_e + (size_t)l * HID);
    float s = 0.f;
#pragma unroll
    for (int i = 0; i < 2; i++) {
        float4 x = wr[lane + 32 * i];
        float4 y = ar[lane + 32 * i];
        s += x.x * y.x + x.y * y.y + x.z * y.z + x.w * y.w;
    }
#pragma unroll
    for (int o = 16; o; o >>= 1) s += __shfl_xor_sync(~0u, s, o);
    if (!lane) Ve[l * EDIM + j] = s;
}

// edge logits: one warp per 4 consecutive edges — sVe smem reads amortized 4x.
__global__ __launch_bounds__(256) void edge_dots4(const float* __restrict__ edge_attr,
                                                  float* __restrict__ out) {
    __shared__ float4 sVe[NL][EDIM / 4];   // 18 KB
    for (int i = threadIdx.x; i < NL * EDIM / 4; i += blockDim.x)
        ((float4*)sVe)[i] = ((const float4*)g_Ve)[i];
    __syncthreads();
    int w = (blockIdx.x * blockDim.x + threadIdx.x) >> 5;
    int lane = threadIdx.x & 31;
    int e0 = w * 4;
    if (e0 >= NE) return;
    const float4* row = (const float4*)edge_attr;

    float acc[NL][4];
#pragma unroll
    for (int l = 0; l < NL; l++)
#pragma unroll
        for (int j = 0; j < 4; j++) acc[l][j] = 0.f;

#pragma unroll
    for (int i = 0; i < 6; i++) {
        int p = lane + 32 * i;
        float4 v0 = row[(size_t)(e0 + 0) * (EDIM / 4) + p];
        float4 v1 = row[(size_t)(e0 + 1) * (EDIM / 4) + p];
        float4 v2 = row[(size_t)(e0 + 2) * (EDIM / 4) + p];
        float4 v3 = row[(size_t)(e0 + 3) * (EDIM / 4) + p];
#pragma unroll
        for (int l = 0; l < NL; l++) {
            float4 u = sVe[l][p];
            acc[l][0] += v0.x * u.x + v0.y * u.y + v0.z * u.z + v0.w * u.w;
            acc[l][1] += v1.x * u.x + v1.y * u.y + v1.z * u.z + v1.w * u.w;
            acc[l][2] += v2.x * u.x + v2.y * u.y + v2.z * u.z + v2.w * u.w;
            acc[l][3] += v3.x * u.x + v3.y * u.y + v3.z * u.z + v3.w * u.w;
        }
    }
#pragma unroll
    for (int l = 0; l < NL; l++)
#pragma unroll
        for (int j = 0; j < 4; j++) {
            float a = acc[l][j];
#pragma unroll
            for (int o = 16; o; o >>= 1) a += __shfl_xor_sync(~0u, a, o);
            if (!lane) out[(size_t)l * NE + e0 + j] = a;
        }
}

__global__ void node_dots(const float* __restrict__ h, const float* __restrict__ as_,
                          const float* __restrict__ ad_, float* __restrict__ s,
                          float* __restrict__ d) {
    int w = (blockIdx.x * blockDim.x + threadIdx.x) >> 5;
    int lane = threadIdx.x & 31;
    if (w >= NN) return;
    const float4* row = (const float4*)(h + (size_t)w * HID);
    const float4* A = (const float4*)as_;
    const float4* D = (const float4*)ad_;
    float ss = 0.f, dd = 0.f;
#pragma unroll
    for (int i = 0; i < 2; i++) {
        float4 v = row[lane + 32 * i];
        float4 a = A[lane + 32 * i];
        float4 b = D[lane + 32 * i];
        ss += v.x * a.x + v.y * a.y + v.z * a.z + v.w * a.w;
        dd += v.x * b.x + v.y * b.y + v.z * b.z + v.w * b.w;
    }
#pragma unroll
    for (int o = 16; o; o >>= 1) {
        ss += __shfl_xor_sync(~0u, ss, o);
        dd += __shfl_xor_sync(~0u, dd, o);
    }
    if (!lane) { s[w] = ss; d[w] = dd; }
}

__global__ void init_md(float* __restrict__ mx, float* __restrict__ dn) {
    int i = blockIdx.x * blockDim.x + threadIdx.x;
    if (i < NN) { mx[i] = -1e30f; dn[i] = 0.f; }
}

__global__ void zero_f4(float4* __restrict__ p, int n4) {
    int i = blockIdx.x * blockDim.x + threadIdx.x;
    if (i < n4) p[i] = make_float4(0.f, 0.f, 0.f, 0.f);
}

__global__ void alpha_max(const int* __restrict__ ei, const float* __restrict__ s,
                          const float* __restrict__ d, const float* __restrict__ ee,
                          float* __restrict__ alpha, float* __restrict__ mx) {
    int e = blockIdx.x * blockDim.x + threadIdx.x;
    if (e >= NE) return;
    int src = ei[e];
    int dst = ei[NE + e];
    float a = s[src] + d[dst] + ee[e];
    a = a > 0.f ? a : 0.2f * a;
    alpha[e] = a;
    atomicMaxF(&mx[dst], a);
}

// fused: ea = exp(alpha - mx[dst]); dn[dst] += ea; out[dst] += ea * h[src]
__global__ void scatter_ea(const int* __restrict__ ei, const float* __restrict__ h,
                           const float* __restrict__ alpha, const float* __restrict__ mx,
                           float* __restrict__ dn, float* __restrict__ out) {
    int w = (blockIdx.x * blockDim.x + threadIdx.x) >> 5;
    int lane = threadIdx.x & 31;
    if (w >= NE) return;
    int src = ei[w];
    int dst = ei[NE + w];
    float eaV = __expf(alpha[w] - mx[dst]);
    if (!lane) atomicAdd(&dn[dst], eaV);
    const float4* hs = (const float4*)(h + (size_t)src * HID);
    float* ob = out + (size_t)dst * HID;
#pragma unroll
    for (int i = 0; i < 2; i++) {
        int p = lane + 32 * i;
        float4 v = hs[p];
        float x = v.x * eaV, y = v.y * eaV, z = v.z * eaV, u = v.w * eaV;
        asm volatile("red.global.add.v4.f32 [%0], {%1,%2,%3,%4};"
                     :: "l"(ob + p * 4), "f"(x), "f"(y), "f"(z), "f"(u)
                     : "memory");
    }
}

// ---------------- launch ----------------
extern "C" void kernel_launch(void* const* d_in, const int* in_sizes, int n_in,
                              void* d_out, int out_size) {
    const float* x    = (const float*)d_in[0];
    const int*   ei   = (const int*)d_in[1];
    const float* eatt = (const float*)d_in[2];
    const float* W1   = (const float*)d_in[3];
    const float* W2   = (const float*)d_in[4];
    const float* Wc   = (const float*)d_in[5];
    const float* We   = (const float*)d_in[6];
    const float* a_s  = (const float*)d_in[7];
    const float* a_d  = (const float*)d_in[8];
    const float* a_e  = (const float*)d_in[9];
    const float* bias = (const float*)d_in[10];
    const float* W3   = (const float*)d_in[11];
    float*       out  = (float*)d_out;

    float *p_hl, *p_hn, *p_ee, *p_ea, *p_s, *p_d, *p_mx, *p_dn, *p_Ve;
    float *p_W12, *p_W012, *p_Ws;
    __nv_bfloat16 *p_Ahi, *p_Alo, *p_Bthi, *p_Btlo;
    cudaGetSymbolAddress((void**)&p_hl, g_hl);
    cudaGetSymbolAddress((void**)&p_hn, g_hn);
    cudaGetSymbolAddress((void**)&p_ee, g_ee);
    cudaGetSymbolAddress((void**)&p_ea, g_ea);
    cudaGetSymbolAddress((void**)&p_s, g_s);
    cudaGetSymbolAddress((void**)&p_d, g_d);
    cudaGetSymbolAddress((void**)&p_mx, g_mx);
    cudaGetSymbolAddress((void**)&p_dn, g_dn);
    cudaGetSymbolAddress((void**)&p_Ve, g_Ve);
    cudaGetSymbolAddress((void**)&p_W12, g_W12);
    cudaGetSymbolAddress((void**)&p_W012, g_W012);
    cudaGetSymbolAddress((void**)&p_Ws, g_Wsum);
    cudaGetSymbolAddress((void**)&p_Ahi, g_Ahi);
    cudaGetSymbolAddress((void**)&p_Alo, g_Alo);
    cudaGetSymbolAddress((void**)&p_Bthi, g_Bthi);
    cudaGetSymbolAddress((void**)&p_Btlo, g_Btlo);

    cudaFuncSetAttribute(mma_gemm2, cudaFuncAttributeMaxDynamicSharedMemorySize,
                         2 * STG * (int)sizeof(__nv_bfloat16));
    const size_t smem_sz = 2 * STG * sizeof(__nv_bfloat16);

    const int MBY = (NN + 127) / 128;
    const dim3 gemm_grid(2, MBY);

    // ---- one-time precompute ----
    sgemm128<<<dim3(2, 2), 256>>>(W1, W2, p_W12, HID);
    sgemm128<<<dim3(2, 2), 256>>>(p_W12, Wc, p_W012, HID);
    wsum_kernel<<<(HID * HID + 255) / 256, 256>>>(W3, p_Ws);
    split_W<<<(7 * HID * HID + 255) / 256, 256>>>(p_W012, Wc, p_Ws, p_Bthi, p_Btlo);
    compute_Ve<<<(NL * EDIM * 32 + 255) / 256, 256>>>(We, a_e, p_Ve);
    edge_dots4<<<((NE / 4) * 32 + 255) / 256, 256>>>(eatt, p_ee);

    // A = split(x)
    split_bias<<<(NN * HID / 4 + 255) / 256, 256>>>(x, nullptr, nullptr, 0,
                                                    p_Ahi, p_Alo);

    for (int l = 0; l < NL; l++) {
        mma_gemm2<<<gemm_grid, 256, smem_sz>>>(
            p_Ahi, p_Alo,
            p_Bthi + (size_t)l * HID * HID, p_Btlo + (size_t)l * HID * HID,
            p_hl, NN);
        node_dots<<<(NN * 32 + 255) / 256, 256>>>(p_hl, a_s + l * HID, a_d + l * HID,
                                                  p_s, p_d);
        init_md<<<(NN + 255) / 256, 256>>>(p_mx, p_dn);
        zero_f4<<<(NN * HID / 4 + 255) / 256, 256>>>((float4*)p_hn, NN * HID / 4);
        alpha_max<<<(NE + 255) / 256, 256>>>(ei, p_s, p_d, p_ee + (size_t)l * NE,
                                             p_ea, p_mx);
        scatter_ea<<<(NE * 32 + 255) / 256, 256>>>(ei, p_hl, p_ea, p_mx, p_dn, p_hn);
        // A = split(hn/dn + bias), relu before the final multiply
        split_bias<<<(NN * HID / 4 + 255) / 256, 256>>>(p_hn, p_dn, bias + l * HID,
                                                        (l == NL - 1) ? 1 : 0,
                                                        p_Ahi, p_Alo);
    }

    // out = relu(h) @ (W3a + W3b)
    mma_gemm2<<<gemm_grid, 256, smem_sz>>>(
        p_Ahi, p_Alo,
        p_Bthi + (size_t)6 * HID * HID, p_Btlo + (size_t)6 * HID * HID,
        out, NN);
}